// round 1
// baseline (speedup 1.0000x reference)
#include <cuda_runtime.h>

// DispCorrM: out[b,d,h,w] = (1/C) * sum_c L[b,c,h,w] * R[b,c,h,w-d]   (0 if w<d)
// x: (B, 2C, H, W) fp32, L = x[:, :C], R = x[:, C:]
// Fixed shapes: B=4, C=32, H=256, W=512, D=64.

#define BB 4
#define CC 32
#define HH 256
#define WW 512
#define DD 64

#define TW 128           // w-tile per block
#define RW (64 + TW)     // R tile width incl. 64-col left halo/zero-pad
#define ND 16            // d's per thread (per warp-group)
#define NW 4             // w's per thread

__global__ __launch_bounds__(128)
void disp_corr_kernel(const float* __restrict__ x, float* __restrict__ out) {
    __shared__ float Lsh[CC][TW];   // 16 KB
    __shared__ float Rsh[CC][RW];   // 24 KB

    const int tile = blockIdx.x;            // 0..3
    const int h    = blockIdx.y;            // 0..255
    const int b    = blockIdx.z;            // 0..3
    const int tile_start = tile * TW;
    const int tid = threadIdx.x;

    const size_t chan_stride = (size_t)HH * WW;

    // ---- Load L tile: channels 0..31, w in [tile_start, tile_start+TW) ----
    {
        const float* Lg = x + ((size_t)(b * 2 * CC) * HH + h) * WW + tile_start;
        #pragma unroll
        for (int k = 0; k < (CC * TW / 4) / 128; k++) {
            int idx = k * 128 + tid;
            int c  = idx / (TW / 4);
            int w4 = idx % (TW / 4);
            float4 v = *(const float4*)(Lg + (size_t)c * chan_stride + 4 * w4);
            *(float4*)&Lsh[c][4 * w4] = v;
        }
    }

    // ---- Load R tile: channels 32..63, local j maps to w = tile_start + j - 64 ----
    {
        const float* Rg = x + ((size_t)(b * 2 * CC + CC) * HH + h) * WW;
        for (int idx = tid; idx < CC * (RW / 4); idx += 128) {
            int c  = idx / (RW / 4);
            int j4 = idx % (RW / 4);
            int wg = tile_start + 4 * j4 - 64;
            float4 v;
            if (wg >= 0) {
                v = *(const float4*)(Rg + (size_t)c * chan_stride + wg);
            } else {
                v = make_float4(0.f, 0.f, 0.f, 0.f);
            }
            *(float4*)&Rsh[c][4 * j4] = v;
        }
    }

    __syncthreads();

    const int lane = tid & 31;
    const int warp = tid >> 5;            // 0..3
    const int w0 = lane * 4;              // 0..124 (stride-16B across lanes: conflict-free LDS.128)
    const int d0 = warp * ND;             // 0,16,32,48

    float acc[ND][NW];
    #pragma unroll
    for (int i = 0; i < ND; i++)
        #pragma unroll
        for (int j = 0; j < NW; j++) acc[i][j] = 0.f;

    // R shared index for (w0+i, d0+dd) is 64 + w0 + i - d0 - dd = rbase + 16 - dd + i
    const int rbase = 64 + w0 - d0 - 16;   // multiple of 4 (w0 mod 4 == 0, d0 mod 16 == 0)

    #pragma unroll 2
    for (int c = 0; c < CC; c++) {
        float4 Lv = *(const float4*)&Lsh[c][w0];

        float r[20];
        #pragma unroll
        for (int q = 0; q < 5; q++)
            *(float4*)&r[4 * q] = *(const float4*)&Rsh[c][rbase + 4 * q];

        #pragma unroll
        for (int dd = 0; dd < ND; dd++) {
            acc[dd][0] = fmaf(Lv.x, r[16 - dd + 0], acc[dd][0]);
            acc[dd][1] = fmaf(Lv.y, r[16 - dd + 1], acc[dd][1]);
            acc[dd][2] = fmaf(Lv.z, r[16 - dd + 2], acc[dd][2]);
            acc[dd][3] = fmaf(Lv.w, r[16 - dd + 3], acc[dd][3]);
        }
    }

    // ---- Epilogue: scale by 1/C and store (float4, contiguous per warp) ----
    const float inv_c = 1.0f / (float)CC;
    float* og = out + (((size_t)b * DD + d0) * HH + h) * WW + tile_start + w0;
    #pragma unroll
    for (int dd = 0; dd < ND; dd++) {
        float4 v = make_float4(acc[dd][0] * inv_c, acc[dd][1] * inv_c,
                               acc[dd][2] * inv_c, acc[dd][3] * inv_c);
        *(float4*)(og + (size_t)dd * chan_stride) = v;
    }
}

extern "C" void kernel_launch(void* const* d_in, const int* in_sizes, int n_in,
                              void* d_out, int out_size) {
    const float* x = (const float*)d_in[0];
    float* out = (float*)d_out;
    dim3 grid(WW / TW, HH, BB);   // (4, 256, 4) = 4096 blocks
    disp_corr_kernel<<<grid, 128>>>(x, out);
}